// round 13
// baseline (speedup 1.0000x reference)
#include <cuda_runtime.h>
#include <cuda_bf16.h>
#include <cstdint>

#define B_   4
#define SM_  1024
#define SI_  4096
#define D_   256
#define H_   8
#define FF_  1024
#define MROWS (B_*SM_)
#define IROWS (B_*SI_)
#define NSP   2560          /* packed state-proj width: 512 kv + 2048 q */

typedef __nv_bfloat16  bf16;
typedef __nv_bfloat162 bf162;

// ---------------- scratch -------------------------------------------------
__device__ bf16  g_ib  [IROWS*D_];
__device__ bf16  g_sb  [MROWS*D_];
__device__ bf16  g_Wspb[D_*NSP];          // packed Wk|Wv|Wq0..7
__device__ float g_bsp [NSP];             // packed bk|bv|bq
__device__ bf16  g_Wob [H_*D_*D_];
__device__ bf16  g_Winb[D_*FF_];
__device__ bf16  g_Wgnlb[FF_*FF_];
__device__ bf16  g_Wglb [FF_*FF_];
__device__ bf16  g_Wgob [FF_*D_];
__device__ bf16  g_kvb [IROWS*512];       // ik|iv packed rows (bf16)
__device__ bf16  g_skq [MROWS*NSP];       // mk|mv|q packed rows
__device__ uint8_t g_q8 [H_*MROWS*256];   // q in e4m3, [h][m][d]
__device__ uint8_t g_k8 [IROWS*256];      // ik in e4m3, [b*SI+s][d]
__device__ uint8_t g_v8T[B_*256*SI_];     // iv in e4m3, transposed [b][d][s]
__device__ bf16  g_ccb [MROWS*H_*D_];
__device__ float g_y   [MROWS*D_];
__device__ float g_x   [MROWS*D_];
__device__ bf16  g_xb  [MROWS*D_];
__device__ bf16  g_hb  [MROWS*FF_];
__device__ bf16  g_gb  [MROWS*FF_];
__device__ float g_y2  [MROWS*D_];

// ---------------- helpers --------------------------------------------------
__device__ __forceinline__ uint32_t sptr(const void* p){
    return (uint32_t)__cvta_generic_to_shared(p);
}
__device__ __forceinline__ float fexp2(float x){
    float y; asm("ex2.approx.f32 %0, %1;" : "=f"(y) : "f"(x)); return y;
}
__device__ __forceinline__ uint32_t pack_e4m3_4(float a, float b, float c, float d){
    uint16_t lo, hi;
    asm("cvt.rn.satfinite.e4m3x2.f32 %0, %1, %2;" : "=h"(lo) : "f"(b), "f"(a));
    asm("cvt.rn.satfinite.e4m3x2.f32 %0, %1, %2;" : "=h"(hi) : "f"(d), "f"(c));
    return (uint32_t)lo | ((uint32_t)hi<<16);
}
__device__ __forceinline__ uint16_t pack_e4m3_2(float a, float b){
    uint16_t r;
    asm("cvt.rn.satfinite.e4m3x2.f32 %0, %1, %2;" : "=h"(r) : "f"(b), "f"(a));
    return r;
}
__device__ __forceinline__ uint8_t fp8_1(float a){
    uint16_t r;
    asm("cvt.rn.satfinite.e4m3x2.f32 %0, %1, %2;" : "=h"(r) : "f"(0.f), "f"(a));
    return (uint8_t)r;
}
__device__ __forceinline__ void ldsm4(uint32_t a[4], uint32_t addr){
    asm volatile("ldmatrix.sync.aligned.m8n8.x4.shared.b16 {%0,%1,%2,%3},[%4];"
        : "=r"(a[0]),"=r"(a[1]),"=r"(a[2]),"=r"(a[3]) : "r"(addr));
}
__device__ __forceinline__ void ldsm4t(uint32_t a[4], uint32_t addr){
    asm volatile("ldmatrix.sync.aligned.m8n8.x4.trans.shared.b16 {%0,%1,%2,%3},[%4];"
        : "=r"(a[0]),"=r"(a[1]),"=r"(a[2]),"=r"(a[3]) : "r"(addr));
}
__device__ __forceinline__ void mma16816(float c[4], const uint32_t a[4], const uint32_t b[2]){
    asm volatile("mma.sync.aligned.m16n8k16.row.col.f32.bf16.bf16.f32 "
        "{%0,%1,%2,%3},{%4,%5,%6,%7},{%8,%9},{%0,%1,%2,%3};"
        : "+f"(c[0]),"+f"(c[1]),"+f"(c[2]),"+f"(c[3])
        : "r"(a[0]),"r"(a[1]),"r"(a[2]),"r"(a[3]),"r"(b[0]),"r"(b[1]));
}
__device__ __forceinline__ void mma_e4m3(float c[4], const uint32_t a[4], const uint32_t b[2]){
    asm volatile("mma.sync.aligned.m16n8k32.row.col.f32.e4m3.e4m3.f32 "
        "{%0,%1,%2,%3},{%4,%5,%6,%7},{%8,%9},{%0,%1,%2,%3};"
        : "+f"(c[0]),"+f"(c[1]),"+f"(c[2]),"+f"(c[3])
        : "r"(a[0]),"r"(a[1]),"r"(a[2]),"r"(a[3]),"r"(b[0]),"r"(b[1]));
}
__device__ __forceinline__ void cp16(uint32_t dst, const void* src){
    asm volatile("cp.async.cg.shared.global [%0],[%1],16;" :: "r"(dst),"l"(src));
}
__device__ __forceinline__ void cpcommit(){ asm volatile("cp.async.commit_group;"); }
__device__ __forceinline__ void cpwait0(){ asm volatile("cp.async.wait_group 0;"); }
__device__ __forceinline__ void cpwait1(){ asm volatile("cp.async.wait_group 1;"); }

// ---------------- cvt kernels ------------------------------------------------
__global__ void cvt_io(const float* __restrict__ input, const float* __restrict__ state){
    int q = blockIdx.x*blockDim.x + threadIdx.x;
    const int NQI = IROWS*D_/4;
    const int NQS = MROWS*D_/4;
    if (q < NQI){
        float4 v = *(const float4*)(input + (size_t)q*4);
        *(bf162*)(g_ib + q*4)   = __floats2bfloat162_rn(v.x,v.y);
        *(bf162*)(g_ib + q*4+2) = __floats2bfloat162_rn(v.z,v.w);
    } else if (q < NQI + NQS){
        int r = q - NQI;
        float4 v = *(const float4*)(state + (size_t)r*4);
        *(bf162*)(g_sb + r*4)   = __floats2bfloat162_rn(v.x,v.y);
        *(bf162*)(g_sb + r*4+2) = __floats2bfloat162_rn(v.z,v.w);
    }
}

__device__ __forceinline__ void cvt4(const float* s, bf16* d){
    float4 v = *(const float4*)s;
    *(bf162*)(d)   = __floats2bfloat162_rn(v.x,v.y);
    *(bf162*)(d+2) = __floats2bfloat162_rn(v.z,v.w);
}

__global__ void cvt_w(const float* __restrict__ Wq, const float* __restrict__ Wo,
                      const float* __restrict__ Win, const float* __restrict__ Wgnl,
                      const float* __restrict__ Wgl, const float* __restrict__ Wgo,
                      const float* __restrict__ Wk, const float* __restrict__ Wv,
                      const float* __restrict__ bk, const float* __restrict__ bv,
                      const float* __restrict__ bq)
{
    int q = blockIdx.x*blockDim.x + threadIdx.x;
    const int S0=131072, S1=131072, S2=65536, S3=262144, S4=262144, S5=65536,
              S6=16384, S7=16384, S8=512, S9=128;
    if (q < S0){ // Wq pack: [h][d][e] -> Wspb[d][512 + h*256 + e]
        int e=q*4; int h=e>>16; int rem=e&65535; int d=rem>>8; int c=rem&255;
        cvt4(Wq + e, g_Wspb + d*NSP + 512 + h*256 + c); return; } q -= S0;
    if (q < S1){ cvt4(Wo + q*4, g_Wob + q*4); return; } q -= S1;
    if (q < S2){ cvt4(Win + q*4, g_Winb + q*4); return; } q -= S2;
    if (q < S3){ cvt4(Wgnl + q*4, g_Wgnlb + q*4); return; } q -= S3;
    if (q < S4){ cvt4(Wgl + q*4, g_Wglb + q*4); return; } q -= S4;
    if (q < S5){ cvt4(Wgo + q*4, g_Wgob + q*4); return; } q -= S5;
    if (q < S6){ int e=q*4, k=e>>8, j=e&255; cvt4(Wk + e, g_Wspb + k*NSP + j); return; } q -= S6;
    if (q < S7){ int e=q*4, k=e>>8, j=e&255; cvt4(Wv + e, g_Wspb + k*NSP + 256 + j); return; } q -= S7;
    if (q < S8){ int j=q*4; *(float4*)(g_bsp + 512 + j) = *(const float4*)(bq + j); return; } q -= S8;
    if (q < S9){
        int j = q*4;
        const float* src = (j < 256) ? (bk + j) : (bv + j - 256);
        *(float4*)(g_bsp + j) = *(const float4*)src;
    }
}

// fp8 conversions: q8 (straight), k8 (straight), v8T (transposed via smem tile)
// blocks [0, 12288): q8/k8 linear quads; blocks [12288, 16384): V transpose tiles
#define NQK_BLOCKS 12288
__global__ void cvt_fp8t(){
    __shared__ uint8_t tile[32][33];
    int blk = blockIdx.x;
    int t = threadIdx.x;
    if (blk < NQK_BLOCKS){
        int q = blk*256 + t;
        const int NQ = H_*MROWS*256/4;
        if (q < NQ){
            int e = q*4;
            int h = e>>20;
            int rem = e & 1048575;
            int m = rem>>8, d = rem&255;
            const bf162* s = (const bf162*)(g_skq + (size_t)m*NSP + 512 + h*256 + d);
            float2 v0 = __bfloat1622float2(s[0]);
            float2 v1 = __bfloat1622float2(s[1]);
            *(uint32_t*)(g_q8 + e) = pack_e4m3_4(v0.x, v0.y, v1.x, v1.y);
        } else {
            int e = (q-NQ)*4;
            int r = e>>8, d = e&255;
            const bf162* s = (const bf162*)(g_kvb + (size_t)r*512 + d);
            float2 v0 = __bfloat1622float2(s[0]);
            float2 v1 = __bfloat1622float2(s[1]);
            *(uint32_t*)(g_k8 + e) = pack_e4m3_4(v0.x, v0.y, v1.x, v1.y);
        }
    } else {
        int bi = blk - NQK_BLOCKS;           // 0..4095
        int b  = bi>>10;
        int rem = bi & 1023;
        int s0 = (rem>>3)*32;                // 0..4064
        int d0 = (rem&7)*32;                 // 0..224
        int tx = t&31, ty = t>>5;            // 32 x 8
        for (int i=ty; i<32; i+=8){
            float v = __bfloat162float(g_kvb[((size_t)b*SI_ + s0+i)*512 + 256 + d0+tx]);
            tile[i][tx] = fp8_1(v);
        }
        __syncthreads();
        for (int i=ty; i<32; i+=8)
            g_v8T[((size_t)b*256 + d0+i)*SI_ + s0+tx] = tile[tx][i];
    }
}

// ---------------- bf16 GEMM (HMMA), 3-stage pipeline, 1 sync/iter ----------
template<int OUTMODE>
__global__ void __launch_bounds__(256) gemm_bf(
    const bf16* __restrict__ A, const bf16* __restrict__ Bw,
    const float* __restrict__ bias, const float* __restrict__ R,
    void* __restrict__ Cout, int M, int N, int K, int ldB)
{
    __shared__ __align__(16) bf16 smA[3][128*32];
    __shared__ __align__(16) bf16 smB[3][32*128];

    const int m0 = blockIdx.y*128, n0 = blockIdx.x*128;
    const int t = threadIdx.x;
    const int w = t>>5, lane = t&31;
    const int wm = w>>1, wn = w&1;

    auto loadA = [&](int st, int k0){
        #pragma unroll
        for (int i=0;i<2;++i){
            int idx = t + i*256;
            int r = idx>>2, c = idx&3;
            int csw = c ^ ((r>>1)&3);
            cp16(sptr(&smA[st][(r*4+csw)*8]), A + (size_t)(m0+r)*K + k0 + c*8);
        }
    };
    auto loadB = [&](int st, int k0){
        #pragma unroll
        for (int i=0;i<2;++i){
            int idx = t + i*256;
            int r = idx>>4, c = idx&15;
            int csw = c ^ (r&7);
            cp16(sptr(&smB[st][(r*16+csw)*8]), Bw + (size_t)(k0+r)*ldB + n0 + c*8);
        }
    };

    float acc[2][8][4] = {};

    const int KT = K>>5;
    loadA(0,0); loadB(0,0); cpcommit();
    if (KT>1){ loadA(1,32); loadB(1,32); } cpcommit();

    for (int kt=0; kt<KT; ++kt){
        cpwait1();
        __syncthreads();
        const int st = kt%3;

        #pragma unroll
        for (int ks=0; ks<2; ++ks){
            uint32_t af[2][4];
            #pragma unroll
            for (int mt=0; mt<2; ++mt){
                int r = wm*32 + mt*16 + (lane&7) + ((lane>>3)&1)*8;
                int c = ks*2 + (lane>>4);
                int csw = c ^ ((r>>1)&3);
                ldsm4(af[mt], sptr(&smA[st][(r*4+csw)*8]));
            }
            #pragma unroll
            for (int np=0; np<4; ++np){
                uint32_t bfr[4];
                int kr = ks*16 + (lane&7) + ((lane>>3)&1)*8;
                int c  = (wn*64 + np*16)/8 + (lane>>4);
                int csw = c ^ (kr&7);
                ldsm4t(bfr, sptr(&smB[st][(kr*16+csw)*8]));
                mma16816(acc[0][np*2+0], af[0], &bfr[0]);
                mma16816(acc[0][np*2+1], af[0], &bfr[2]);
                mma16816(acc[1][np*2+0], af[1], &bfr[0]);
                mma16816(acc[1][np*2+1], af[1], &bfr[2]);
            }
        }
        if (kt+2 < KT){ loadA((kt+2)%3, (kt+2)*32); loadB((kt+2)%3, (kt+2)*32); }
        cpcommit();
    }

    const int rbase = m0 + wm*32 + (lane>>2);
    const int cbase = n0 + wn*64 + (lane&3)*2;
    #pragma unroll
    for (int mt=0; mt<2; ++mt){
        #pragma unroll
        for (int nt=0; nt<8; ++nt){
            int row = rbase + mt*16;
            int col = cbase + nt*8;
            float b0 = bias[col], b1 = bias[col+1];
            float v0 = acc[mt][nt][0]+b0, v1 = acc[mt][nt][1]+b1;
            float v2 = acc[mt][nt][2]+b0, v3 = acc[mt][nt][3]+b1;
            if (OUTMODE==1){
                v0=fmaxf(v0,0.f); v1=fmaxf(v1,0.f); v2=fmaxf(v2,0.f); v3=fmaxf(v3,0.f);
            }
            if (OUTMODE==3){
                float2 r0 = *(const float2*)(R + (size_t)row*N + col);
                float2 r1 = *(const float2*)(R + (size_t)(row+8)*N + col);
                v0+=r0.x; v1+=r0.y; v2+=r1.x; v3+=r1.y;
            }
            if (OUTMODE<=1){
                bf16* C = (bf16*)Cout;
                *(bf162*)(C + (size_t)row*N + col)     = __floats2bfloat162_rn(v0,v1);
                *(bf162*)(C + (size_t)(row+8)*N + col) = __floats2bfloat162_rn(v2,v3);
            } else {
                float* C = (float*)Cout;
                *(float2*)(C + (size_t)row*N + col)     = make_float2(v0,v1);
                *(float2*)(C + (size_t)(row+8)*N + col) = make_float2(v2,v3);
            }
        }
    }
}

// ---------------- fused FFN gate: C = relu(A@B1+b1) * (A@B2+b2) ------------
__global__ void __launch_bounds__(256) dualgate(
    const bf16* __restrict__ A,
    const bf16* __restrict__ B1, const float* __restrict__ b1,
    const bf16* __restrict__ B2, const float* __restrict__ b2,
    bf16* __restrict__ C, int M, int N, int K)
{
    __shared__ __align__(16) bf16 smA [3][128*32];
    __shared__ __align__(16) bf16 smB1[3][32*64];
    __shared__ __align__(16) bf16 smB2[3][32*64];

    const int m0 = blockIdx.y*128, n0 = blockIdx.x*64;
    const int t = threadIdx.x;
    const int w = t>>5, lane = t&31;
    const int wm = w>>1, wn = w&1;

    auto loadA = [&](int st, int k0){
        #pragma unroll
        for (int i=0;i<2;++i){
            int idx = t + i*256;
            int r = idx>>2, c = idx&3;
            int csw = c ^ ((r>>1)&3);
            cp16(sptr(&smA[st][(r*4+csw)*8]), A + (size_t)(m0+r)*K + k0 + c*8);
        }
    };
    auto loadB = [&](int st, int k0){
        int r = t>>3, c = t&7;
        int csw = c ^ (r&7);
        cp16(sptr(&smB1[st][(r*8+csw)*8]), B1 + (size_t)(k0+r)*N + n0 + c*8);
        cp16(sptr(&smB2[st][(r*8+csw)*8]), B2 + (size_t)(k0+r)*N + n0 + c*8);
    };

    float acc1[2][4][4] = {};
    float acc2[2][4][4] = {};

    const int KT = K>>5;
    loadA(0,0); loadB(0,0); cpcommit();
    if (KT>1){ loadA(1,32); loadB(1,32); } cpcommit();

    for (int kt=0; kt<KT; ++kt){
        cpwait1();
        __syncthreads();
        const int st = kt%3;

        #pragma unroll
        for (int ks=0; ks<2; ++ks){
            uint32_t af[2][4];
            #pragma unroll
            for (int mt=0; mt<2; ++mt){
                int r = wm*32 + mt*16 + (lane&7) + ((lane>>3)&1)*8;
                int c = ks*2 + (lane>>4);
                int csw = c ^ ((r>>1)&3);
                ldsm4(af[mt], sptr(&smA[st][(r*4+csw)*8]));
            }
            #pragma unroll
            for (int np=0; np<2; ++np){
                int kr = ks*16 + (lane&7) + ((lane>>3)&1)*8;
                int c  = (wn*32 + np*16)/8 + (lane>>4);
                int csw = c ^ (kr&7);
                uint32_t f1[4], f2[4];
                ldsm4t(f1, sptr(&smB1[st][(kr*8+csw)*8]));
                ldsm4t(f2, sptr(&smB2[st][(kr*8+csw)*8]));
                mma16816(acc1[0][np*2+0], af[0], &f1[0]);
                mma16816(acc1[0][np*2+1], af[0], &f1[2]);
                mma16816(acc1[1][np*2+0], af[1], &f1[0]);
                mma16816(acc1[1][np*2+1], af[1], &f1[2]);
                mma16816(acc2[0][np*2+0], af[0], &f2[0]);
                mma16816(acc2[0][np*2+1], af[0], &f2[2]);
                mma16816(acc2[1][np*2+0], af[1], &f2[0]);
                mma16816(acc2[1][np*2+1], af[1], &f2[2]);
            }
        }
        if (kt+2 < KT){ loadA((kt+2)%3, (kt+2)*32); loadB((kt+2)%3, (kt+2)*32); }
        cpcommit();
    }

    const int rbase = m0 + wm*32 + (lane>>2);
    const int cbase = n0 + wn*32 + (lane&3)*2;
    #pragma unroll
    for (int mt=0; mt<2; ++mt){
        #pragma unroll
        for (int nt=0; nt<4; ++nt){
            int row = rbase + mt*16;
            int col = cbase + nt*8;
            float c10 = b1[col], c11 = b1[col+1];
            float c20 = b2[col], c21 = b2[col+1];
            float v0 = fmaxf(acc1[mt][nt][0]+c10, 0.f)*(acc2[mt][nt][0]+c20);
            float v1 = fmaxf(acc1[mt][nt][1]+c11, 0.f)*(acc2[mt][nt][1]+c21);
            float v2 = fmaxf(acc1[mt][nt][2]+c10, 0.f)*(acc2[mt][nt][2]+c20);
            float v3 = fmaxf(acc1[mt][nt][3]+c11, 0.f)*(acc2[mt][nt][3]+c21);
            *(bf162*)(C + (size_t)row*N + col)     = __floats2bfloat162_rn(v0,v1);
            *(bf162*)(C + (size_t)(row+8)*N + col) = __floats2bfloat162_rn(v2,v3);
        }
    }
}

// ---------------- flash attention v6: full fp8 (QK + PV), merged pipeline ---
// smem: Q8 32KB | K8 2x16KB | V8T 2x20KB(80B rows) | P8 2x10KB(80B rows) | stats
#define FQ8_OFF    0
#define FK8_OFF(s) (32768 + (s)*16384)
#define FV8_OFF(s) (65536 + (s)*20480)
#define FP8_OFF(s) (106496 + (s)*10240)
#define FST_OFF    126976
#define FLASH_SMEM 129536
#define NT_        (SI_/64)
#define EXSC       0.09016844f   /* log2(e)/16 */

__global__ void __launch_bounds__(512,1) flash_f8()
{
    extern __shared__ __align__(16) char sm[];
    const uint32_t smb = sptr(sm);
    float* es_s   = (float*)(sm + FST_OFF);
    float* rsum_s = (float*)(sm + FST_OFF + 512);
    float* psum_s = (float*)(sm + FST_OFF + 1024);

    const int t = threadIdx.x, w = t>>5, lane = t&31;
    const int h = blockIdx.y, b = blockIdx.z;
    const int m0 = blockIdx.x*128;

    // fp8 QK tiles: row r, 16B chunk c, XOR swizzle
    auto f8off = [](int r, int c){ return (r*16 + (c ^ (r&7)))*16; };

    // ---- prologue loads: Q8 + K8(0) + V8(0) in group0, empty group1 ----
    const uint8_t* q8g = g_q8 + ((size_t)h*MROWS + b*SM_ + m0)*256;
    #pragma unroll
    for (int i=0;i<4;++i){
        int idx = t + i*512;             // 0..2047
        int r = idx>>4, c = idx&15;
        cp16(smb + FQ8_OFF + f8off(r,c), q8g + (size_t)r*256 + c*16);
    }
    auto loadK = [&](int tile, int slot){
        const uint8_t* kg = g_k8 + ((size_t)b*SI_ + tile*64)*256;
        #pragma unroll
        for (int i=0;i<2;++i){
            int idx = t + i*512;         // 0..1023
            int r = idx>>4, c = idx&15;
            cp16(smb + FK8_OFF(slot) + f8off(r,c), kg + (size_t)r*256 + c*16);
        }
    };
    auto loadV = [&](int tile, int slot){
        const uint8_t* vg = g_v8T + (size_t)b*256*SI_ + tile*64;
        #pragma unroll
        for (int i=0;i<2;++i){
            int idx = t + i*512;         // 0..1023: r=d row 0..255, c=chunk 0..3
            int r = idx>>2, c = idx&3;
            cp16(smb + FV8_OFF(slot) + r*80 + c*16, vg + (size_t)r*SI_ + c*16);
        }
    };
    loadK(0,0); loadV(0,0); cpcommit();   // g0
    cpcommit();                           // g1 empty (uniform commit count)

    // self-score (bf16 global reads, overlaps cp.async)
    {
        int row = t>>2, quad = t&3;
        const bf162* q2 = (const bf162*)(g_skq + (size_t)(b*SM_ + m0 + row)*NSP + 512 + h*256 + quad*64);
        const bf162* k2 = (const bf162*)(g_skq + (size_t)(b*SM_ + m0 + row)*NSP + quad*64);
        float s = 0.f;
        #pragma unroll
        for (int j=0;j<32;++j){
            float2 qv = __bfloat1622float2(q2[j]);
            float2 kv = __bfloat1622float2(k2[j]);
            s += qv.x*kv.x + qv.y*kv.y;
        }
        s += __shfl_xor_sync(~0u, s, 1);
        s += __shfl_xor_sync(~0u, s, 2);
        if (quad==0) es_s[row] = fexp2(s*EXSC);
    }
    __syncthreads();   // es visible

    // O init = es * mv (bf16 from packed buffer)
    const int mh = w>>2, nq = w&3;
    float o[2][8][4];
    {
        const bf16* mvb = g_skq + (size_t)(b*SM_ + m0)*NSP + 256;
        #pragma unroll
        for (int mt=0;mt<2;++mt){
            int r0 = mh*32 + mt*16 + (lane>>2);
            float e0 = es_s[r0], e1 = es_s[r0+8];
            #pragma unroll
            for (int nt=0;nt<8;++nt){
                int col = nq*64 + nt*8 + (lane&3)*2;
                float2 f0 = __bfloat1622float2(*(const bf162*)(mvb + (size_t)r0*NSP + col));
                float2 f1 = __bfloat1622float2(*(const bf162*)(mvb + (size_t)(r0+8)*NSP + col));
                o[mt][nt][0]=e0*f0.x; o[mt][nt][1]=e0*f0.y;
                o[mt][nt][2]=e1*f1.x; o[mt][nt][3]=e1*f1.y;
            }
        }
    }

    const int sw_m = w>>1, sw_n = w&1;
    float ps0 = 0.f, ps1 = 0.f;

    // ---- merged pipeline: body bb = S(bb) + PV(bb-1) + exp(bb), all fp8 ----
    for (int bb=0; bb<=NT_; ++bb){
        cpwait1();
        __syncthreads();

        if (bb+1 < NT_) loadK(bb+1, (bb+1)&1);
        cpcommit();

        float sa[4][4] = {};
        if (bb < NT_){
            const uint32_t Kb = smb + FK8_OFF(bb&1);
            #pragma unroll
            for (int ks=0; ks<8; ++ks){
                uint32_t af[4];
                {
                    int r = sw_m*16 + (lane&7) + ((lane>>3)&1)*8;
                    int c = ks*2 + (lane>>4);
                    ldsm4(af, smb + FQ8_OFF + f8off(r,c));
                }
                #pragma unroll
                for (int np=0; np<2; ++np){
                    uint32_t bfr[4];
                    int r = sw_n*32 + np*16 + ((lane>>4)&1)*8 + (lane&7);
                    int c = ks*2 + ((lane>>3)&1);
                    ldsm4(bfr, Kb + f8off(r,c));
                    mma_e4m3(sa[np*2+0], af, &bfr[0]);
                    mma_e4m3(sa[np*2+1], af, &bfr[2]);
                }
            }
        }

        if (bb >= 1){
            const uint32_t Vb = smb + FV8_OFF((bb-1)&1);
            const uint32_t Pb = smb + FP8_OFF((bb-1)&1);
            #pragma unroll
            for (int ks=0; ks<2; ++ks){
                uint32_t aP[2][4];
                #pragma unroll
                for (int mt=0;mt<2;++mt){
                    int r = mh*32 + mt*16 + (lane&7) + ((lane>>3)&1)*8;
                    int c = ks*2 + (lane>>4);
                    ldsm4(aP[mt], Pb + r*80 + c*16);
                }
                #pragma unroll
                for (int np=0;np<4;++np){
                    uint32_t bfr[4];
                    int r = nq*64 + np*16 + ((lane>>4)&1)*8 + (lane&7);
                    int c = ks*2 + ((lane>>3)&1);
                    ldsm4(bfr, Vb + r*80 + c*16);
                    mma_e4m3(o[0][np*2+0], aP[0], &bfr[0]);
                    mma_e4m3(o[0][np*2+1], aP[0], &bfr[2]);
                    mma_e4m3(o[1][np*2+0], aP[1], &bfr[0]);
                    mma_e4m3(o[1][np*2+1], aP[1], &bfr[2]);
                }
            }
        }

        if (bb < NT_){
            uint8_t* P8 = (uint8_t*)(sm + FP8_OFF(bb&1));
            int r0 = sw_m*16 + (lane>>2);
            #pragma unroll
            for (int i4=0;i4<4;++i4){
                float p0 = fexp2(sa[i4][0]*EXSC);
                float p1 = fexp2(sa[i4][1]*EXSC);
                float p2 = fexp2(sa[i4][2]*EXSC);
                float p3 = fexp2(sa[i4][3]*EXSC);
                ps0 += p0 + p1;
                ps1 += p2 + p3;
                int c = sw_n*32 + i4*8 + (lane&3)*2;
                *(uint16_t*)(P8 + r0*80 + c)     = pack_e4m3_2(p0, p1);
                *(uint16_t*)(P8 + (r0+8)*80 + c) = pack_e4m3_2(p2, p3);
            }
        }

        __syncthreads();
        if (bb+1 < NT_) loadV(bb+1, (bb+1)&1);
        cpcommit();
    }

    // row-sum reduce + self term
    ps0 += __shfl_xor_sync(~0u, ps0, 1);
    ps0 += __shfl_xor_sync(~0u, ps0, 2);
    ps1 += __shfl_xor_sync(~0u, ps1, 1);
    ps1 += __shfl_xor_sync(~0u, ps1, 2);
    if ((lane&3)==0){
        int r0 = sw_m*16 + (lane>>2);
        psum_s[r0*2 + sw_n]     = ps0;
        psum_s[(r0+8)*2 + sw_n] = ps1;
    }
    __syncthreads();
    if (t < 128) rsum_s[t] = es_s[t] + psum_s[t*2] + psum_s[t*2+1];
    __syncthreads();

    // normalize + write concat (bf16)
    #pragma unroll
    for (int mt=0;mt<2;++mt){
        int r0 = mh*32 + mt*16 + (lane>>2);
        float i0 = 1.f/rsum_s[r0], i1 = 1.f/rsum_s[r0+8];
        bf16* c0 = g_ccb + ((size_t)(b*SM_ + m0 + r0)*(H_*D_)) + h*D_;
        bf16* c1 = g_ccb + ((size_t)(b*SM_ + m0 + r0 + 8)*(H_*D_)) + h*D_;
        #pragma unroll
        for (int nt=0;nt<8;++nt){
            int col = nq*64 + nt*8 + (lane&3)*2;
            *(bf162*)(c0+col) = __floats2bfloat162_rn(o[mt][nt][0]*i0, o[mt][nt][1]*i0);
            *(bf162*)(c1+col) = __floats2bfloat162_rn(o[mt][nt][2]*i1, o[mt][nt][3]*i1);
        }
    }
}

// ---------------- LayerNorm ------------------------------------------------
__global__ void ln_kernel(const float* __restrict__ Y, const float* __restrict__ g,
                          const float* __restrict__ bb, float* __restrict__ X,
                          bf16* __restrict__ Xb)
{
    const int row = blockIdx.x;
    const int t = threadIdx.x;
    const float v = Y[(size_t)row*D_ + t];
    __shared__ float red[8];
    __shared__ float stat;

    float s = v;
    #pragma unroll
    for (int o = 16; o; o >>= 1) s += __shfl_xor_sync(0xffffffffu, s, o);
    if ((t & 31) == 0) red[t >> 5] = s;
    __syncthreads();
    if (t == 0) {
        float tot = 0.f;
        #pragma unroll
        for (int i = 0; i < 8; ++i) tot += red[i];
        stat = tot * (1.f / D_);
    }
    __syncthreads();
    const float mean = stat;
    const float d = v - mean;

    s = d * d;
    #pragma unroll
    for (int o = 16; o; o >>= 1) s += __shfl_xor_sync(0xffffffffu, s, o);
    __syncthreads();
    if ((t & 31) == 0) red[t >> 5] = s;
    __syncthreads();
    if (t == 0) {
        float tot = 0.f;
        #pragma unroll
        for (int i = 0; i < 8; ++i) tot += red[i];
        stat = tot * (1.f / D_);
    }
    __syncthreads();
    float out = d * rsqrtf(stat + 1e-6f) * g[t] + bb[t];
    X[(size_t)row*D_ + t] = out;
    if (Xb) Xb[(size_t)row*D_ + t] = __float2bfloat16(out);
}

// ---------------- launch ----------------------------------------------------
extern "C" void kernel_launch(void* const* d_in, const int* in_sizes, int n_in,
                              void* d_out, int out_size)
{
    (void)in_sizes; (void)n_in; (void)out_size;
    const float* state = (const float*)d_in[0];
    const float* input = (const float*)d_in[1];
    const float* Wk    = (const float*)d_in[2];
    const float* bk    = (const float*)d_in[3];
    const float* Wv    = (const float*)d_in[4];
    const float* bv    = (const float*)d_in[5];
    const float* Wq    = (const float*)d_in[6];
    const float* bq    = (const float*)d_in[7];
    const float* Wo    = (const float*)d_in[8];
    const float* bo    = (const float*)d_in[9];
    const float* ln1g  = (const float*)d_in[10];
    const float* ln1b  = (const float*)d_in[11];
    const float* Win   = (const float*)d_in[12];
    const float* bin   = (const float*)d_in[13];
    const float* Wgnl  = (const float*)d_in[14];
    const float* bgnl  = (const float*)d_in[15];
    const float* Wgl   = (const float*)d_in[16];
    const float* bgl   = (const float*)d_in[17];
    const float* Wgo   = (const float*)d_in[18];
    const float* bgo   = (const float*)d_in[19];
    const float* ln2g  = (const float*)d_in[20];
    const float* ln2b  = (const float*)d_in[21];
    float* out = (float*)d_out;

    bf16 *ib,*sb,*Wspb,*Wob,*Winb,*Wgnlb,*Wglb,*Wgob;
    bf16 *kvb,*skq,*ccb,*xb,*hb,*gb;
    float *bsp,*y,*x,*y2;
    cudaGetSymbolAddress((void**)&ib,   g_ib);
    cudaGetSymbolAddress((void**)&sb,   g_sb);
    cudaGetSymbolAddress((void**)&Wspb, g_Wspb);
    cudaGetSymbolAddress((void**)&bsp,  g_bsp);
    cudaGetSymbolAddress((void**)&Wob,  g_Wob);
    cudaGetSymbolAddress((void**)&Winb, g_Winb);
    cudaGetSymbolAddress((void**)&Wgnlb,g_Wgnlb);
    cudaGetSymbolAddress((void**)&Wglb, g_Wglb);
    cudaGetSymbolAddress((void**)&Wgob, g_Wgob);
    cudaGetSymbolAddress((void**)&kvb,  g_kvb);
    cudaGetSymbolAddress((void**)&skq,  g_skq);
    cudaGetSymbolAddress((void**)&ccb,  g_ccb);
    cudaGetSymbolAddress((void**)&y,    g_y);
    cudaGetSymbolAddress((void**)&x,    g_x);
    cudaGetSymbolAddress((void**)&xb,   g_xb);
    cudaGetSymbolAddress((void**)&hb,   g_hb);
    cudaGetSymbolAddress((void**)&gb,   g_gb);
    cudaGetSymbolAddress((void**)&y2,   g_y2);

    cudaFuncSetAttribute(flash_f8, cudaFuncAttributeMaxDynamicSharedMemorySize, FLASH_SMEM);

    dim3 blk(256);
    // 0: io converts
    cvt_io<<<((IROWS+MROWS)*D_/4 + 255)/256, 256>>>(input, state);
    // 1: weight converts + packing
    cvt_w<<<(950912 + 255)/256, 256>>>(Wq, Wo, Win, Wgnl, Wgl, Wgo, Wk, Wv, bk, bv, bq);
    // 2: state merged projection [kv|q]
    gemm_bf<0><<<dim3(NSP/128, MROWS/128), blk>>>(sb, Wspb, bsp, nullptr, skq, MROWS, NSP, D_, NSP);
    // 3: input K|V projection (one launch, grid 512)
    gemm_bf<0><<<dim3(4, IROWS/128), blk>>>(ib, Wspb, bsp, nullptr, kvb, IROWS, 512, D_, NSP);
    // 4: fp8 conversions q8/k8 + V transpose to v8T
    cvt_fp8t<<<16384, 256>>>();
    // 5: flash attention (full fp8)  <- ncu -s 5 -c 1 captures this
    flash_f8<<<dim3(SM_/128, H_, B_), 512, FLASH_SMEM>>>();
    // output proj + residual, LN1
    gemm_bf<3><<<dim3(2, MROWS/128), blk>>>(ccb, Wob, bo, state, y, MROWS, D_, H_*D_, D_);
    ln_kernel<<<MROWS, D_>>>(y, ln1g, ln1b, x, xb);
    // FFN
    gemm_bf<1><<<dim3(FF_/128, MROWS/128), blk>>>(xb, Winb, bin, nullptr, hb, MROWS, FF_, D_, FF_);
    dualgate<<<dim3(FF_/64, MROWS/128), blk>>>(hb, Wgnlb, bgnl, Wglb, bgl, gb, MROWS, FF_, FF_);
    gemm_bf<3><<<dim3(2, MROWS/128), blk>>>(gb, Wgob, bgo, x, y2, MROWS, D_, FF_, D_);
    ln_kernel<<<MROWS, D_>>>(y2, ln2g, ln2b, out, nullptr);
}

// round 14
// speedup vs baseline: 1.1347x; 1.1347x over previous
#include <cuda_runtime.h>
#include <cuda_bf16.h>
#include <cstdint>

#define B_   4
#define SM_  1024
#define SI_  4096
#define D_   256
#define H_   8
#define FF_  1024
#define MROWS (B_*SM_)
#define IROWS (B_*SI_)
#define NSP   2560          /* packed state-proj width: 512 kv + 2048 q */

typedef __nv_bfloat16  bf16;
typedef __nv_bfloat162 bf162;

// ---------------- scratch -------------------------------------------------
__device__ bf16  g_ib  [IROWS*D_];
__device__ bf16  g_sb  [MROWS*D_];
__device__ bf16  g_Wspb[D_*NSP];          // packed Wk|Wv|Wq0..7
__device__ float g_bsp [NSP];             // packed bk|bv|bq
__device__ bf16  g_Wob [H_*D_*D_];
__device__ bf16  g_Winb[D_*FF_];
__device__ bf16  g_Wgnlb[FF_*FF_];
__device__ bf16  g_Wglb [FF_*FF_];
__device__ bf16  g_Wgob [FF_*D_];
__device__ bf16  g_kvb [IROWS*512];       // ik|iv packed rows
__device__ bf16  g_skq [MROWS*NSP];       // mk|mv|q packed rows
__device__ uint8_t g_q8[H_*MROWS*256];    // q in e4m3, [h][m][d]
__device__ uint8_t g_k8[IROWS*256];       // ik in e4m3, [b*SI+s][d]
__device__ bf16  g_ccb [MROWS*H_*D_];
__device__ float g_yp  [2*MROWS*D_];      // Wo split-K partials
__device__ float g_x   [MROWS*D_];
__device__ bf16  g_xb  [MROWS*D_];
__device__ bf16  g_hb  [MROWS*FF_];
__device__ bf16  g_gb  [MROWS*FF_];
__device__ float g_y2p [2*MROWS*D_];      // Wgo split-K partials

// ---------------- helpers --------------------------------------------------
__device__ __forceinline__ uint32_t sptr(const void* p){
    return (uint32_t)__cvta_generic_to_shared(p);
}
__device__ __forceinline__ float fexp2(float x){
    float y; asm("ex2.approx.f32 %0, %1;" : "=f"(y) : "f"(x)); return y;
}
__device__ __forceinline__ uint32_t pack_e4m3_4(float a, float b, float c, float d){
    uint16_t lo, hi;
    asm("cvt.rn.satfinite.e4m3x2.f32 %0, %1, %2;" : "=h"(lo) : "f"(b), "f"(a));
    asm("cvt.rn.satfinite.e4m3x2.f32 %0, %1, %2;" : "=h"(hi) : "f"(d), "f"(c));
    return (uint32_t)lo | ((uint32_t)hi<<16);
}
__device__ __forceinline__ void ldsm4(uint32_t a[4], uint32_t addr){
    asm volatile("ldmatrix.sync.aligned.m8n8.x4.shared.b16 {%0,%1,%2,%3},[%4];"
        : "=r"(a[0]),"=r"(a[1]),"=r"(a[2]),"=r"(a[3]) : "r"(addr));
}
__device__ __forceinline__ void ldsm4t(uint32_t a[4], uint32_t addr){
    asm volatile("ldmatrix.sync.aligned.m8n8.x4.trans.shared.b16 {%0,%1,%2,%3},[%4];"
        : "=r"(a[0]),"=r"(a[1]),"=r"(a[2]),"=r"(a[3]) : "r"(addr));
}
__device__ __forceinline__ void mma16816(float c[4], const uint32_t a[4], const uint32_t b[2]){
    asm volatile("mma.sync.aligned.m16n8k16.row.col.f32.bf16.bf16.f32 "
        "{%0,%1,%2,%3},{%4,%5,%6,%7},{%8,%9},{%0,%1,%2,%3};"
        : "+f"(c[0]),"+f"(c[1]),"+f"(c[2]),"+f"(c[3])
        : "r"(a[0]),"r"(a[1]),"r"(a[2]),"r"(a[3]),"r"(b[0]),"r"(b[1]));
}
__device__ __forceinline__ void mma_e4m3(float c[4], const uint32_t a[4], const uint32_t b[2]){
    asm volatile("mma.sync.aligned.m16n8k32.row.col.f32.e4m3.e4m3.f32 "
        "{%0,%1,%2,%3},{%4,%5,%6,%7},{%8,%9},{%0,%1,%2,%3};"
        : "+f"(c[0]),"+f"(c[1]),"+f"(c[2]),"+f"(c[3])
        : "r"(a[0]),"r"(a[1]),"r"(a[2]),"r"(a[3]),"r"(b[0]),"r"(b[1]));
}
__device__ __forceinline__ void cp16(uint32_t dst, const void* src){
    asm volatile("cp.async.cg.shared.global [%0],[%1],16;" :: "r"(dst),"l"(src));
}
__device__ __forceinline__ void cpcommit(){ asm volatile("cp.async.commit_group;"); }
__device__ __forceinline__ void cpwait0(){ asm volatile("cp.async.wait_group 0;"); }
__device__ __forceinline__ void cpwait1(){ asm volatile("cp.async.wait_group 1;"); }

// ---------------- cvt kernels ------------------------------------------------
__global__ void cvt_io(const float* __restrict__ input, const float* __restrict__ state){
    int q = blockIdx.x*blockDim.x + threadIdx.x;
    const int NQI = IROWS*D_/4;
    const int NQS = MROWS*D_/4;
    if (q < NQI){
        float4 v = *(const float4*)(input + (size_t)q*4);
        *(bf162*)(g_ib + q*4)   = __floats2bfloat162_rn(v.x,v.y);
        *(bf162*)(g_ib + q*4+2) = __floats2bfloat162_rn(v.z,v.w);
    } else if (q < NQI + NQS){
        int r = q - NQI;
        float4 v = *(const float4*)(state + (size_t)r*4);
        *(bf162*)(g_sb + r*4)   = __floats2bfloat162_rn(v.x,v.y);
        *(bf162*)(g_sb + r*4+2) = __floats2bfloat162_rn(v.z,v.w);
    }
}

__device__ __forceinline__ void cvt4(const float* s, bf16* d){
    float4 v = *(const float4*)s;
    *(bf162*)(d)   = __floats2bfloat162_rn(v.x,v.y);
    *(bf162*)(d+2) = __floats2bfloat162_rn(v.z,v.w);
}

__global__ void cvt_w(const float* __restrict__ Wq, const float* __restrict__ Wo,
                      const float* __restrict__ Win, const float* __restrict__ Wgnl,
                      const float* __restrict__ Wgl, const float* __restrict__ Wgo,
                      const float* __restrict__ Wk, const float* __restrict__ Wv,
                      const float* __restrict__ bk, const float* __restrict__ bv,
                      const float* __restrict__ bq)
{
    int q = blockIdx.x*blockDim.x + threadIdx.x;
    const int S0=131072, S1=131072, S2=65536, S3=262144, S4=262144, S5=65536,
              S6=16384, S7=16384, S8=512, S9=128;
    if (q < S0){ // Wq pack: [h][d][e] -> Wspb[d][512 + h*256 + e]
        int e=q*4; int h=e>>16; int rem=e&65535; int d=rem>>8; int c=rem&255;
        cvt4(Wq + e, g_Wspb + d*NSP + 512 + h*256 + c); return; } q -= S0;
    if (q < S1){ cvt4(Wo + q*4, g_Wob + q*4); return; } q -= S1;
    if (q < S2){ cvt4(Win + q*4, g_Winb + q*4); return; } q -= S2;
    if (q < S3){ cvt4(Wgnl + q*4, g_Wgnlb + q*4); return; } q -= S3;
    if (q < S4){ cvt4(Wgl + q*4, g_Wglb + q*4); return; } q -= S4;
    if (q < S5){ cvt4(Wgo + q*4, g_Wgob + q*4); return; } q -= S5;
    if (q < S6){ int e=q*4, k=e>>8, j=e&255; cvt4(Wk + e, g_Wspb + k*NSP + j); return; } q -= S6;
    if (q < S7){ int e=q*4, k=e>>8, j=e&255; cvt4(Wv + e, g_Wspb + k*NSP + 256 + j); return; } q -= S7;
    if (q < S8){ int j=q*4; *(float4*)(g_bsp + 512 + j) = *(const float4*)(bq + j); return; } q -= S8;
    if (q < S9){
        int j = q*4;
        const float* src = (j < 256) ? (bk + j) : (bv + j - 256);
        *(float4*)(g_bsp + j) = *(const float4*)src;
    }
}

// fp8 conversion: q8 from skq q-part, k8 from kvb k-part
__global__ void cvt_fp8(){
    int q = blockIdx.x*blockDim.x + threadIdx.x;
    const int NQ = H_*MROWS*256/4;
    const int NK = IROWS*256/4;
    if (q < NQ){
        int e = q*4;
        int h = e>>20;
        int rem = e & 1048575;
        int m = rem>>8, d = rem&255;
        const bf162* s = (const bf162*)(g_skq + (size_t)m*NSP + 512 + h*256 + d);
        float2 v0 = __bfloat1622float2(s[0]);
        float2 v1 = __bfloat1622float2(s[1]);
        *(uint32_t*)(g_q8 + e) = pack_e4m3_4(v0.x, v0.y, v1.x, v1.y);
    } else if (q < NQ+NK){
        int e = (q-NQ)*4;
        int r = e>>8, d = e&255;
        const bf162* s = (const bf162*)(g_kvb + (size_t)r*512 + d);
        float2 v0 = __bfloat1622float2(s[0]);
        float2 v1 = __bfloat1622float2(s[1]);
        *(uint32_t*)(g_k8 + e) = pack_e4m3_4(v0.x, v0.y, v1.x, v1.y);
    }
}

// ---------------- bf16 GEMM (HMMA), 3-stage pipeline, split-K capable ------
// OUTMODE: 0 bf16, 1 bf16+relu, 2 f32 (+bias only on z==0)
// lda = A row stride; ldB = B row stride; zc = C offset per blockIdx.z slice
template<int OUTMODE>
__global__ void __launch_bounds__(256) gemm_bf(
    const bf16* __restrict__ A, const bf16* __restrict__ Bw,
    const float* __restrict__ bias,
    void* __restrict__ Cout, int M, int N, int K, int ldB, int lda, long zc)
{
    __shared__ __align__(16) bf16 smA[3][128*32];
    __shared__ __align__(16) bf16 smB[3][32*128];

    const int z = blockIdx.z;
    A  += (size_t)z*K;             // K columns per slice
    Bw += (size_t)z*K*ldB;         // K rows per slice
    const float bsel = (z==0) ? 1.f : 0.f;

    const int m0 = blockIdx.y*128, n0 = blockIdx.x*128;
    const int t = threadIdx.x;
    const int w = t>>5, lane = t&31;
    const int wm = w>>1, wn = w&1;

    auto loadA = [&](int st, int k0){
        #pragma unroll
        for (int i=0;i<2;++i){
            int idx = t + i*256;
            int r = idx>>2, c = idx&3;
            int csw = c ^ ((r>>1)&3);
            cp16(sptr(&smA[st][(r*4+csw)*8]), A + (size_t)(m0+r)*lda + k0 + c*8);
        }
    };
    auto loadB = [&](int st, int k0){
        #pragma unroll
        for (int i=0;i<2;++i){
            int idx = t + i*256;
            int r = idx>>4, c = idx&15;
            int csw = c ^ (r&7);
            cp16(sptr(&smB[st][(r*16+csw)*8]), Bw + (size_t)(k0+r)*ldB + n0 + c*8);
        }
    };

    float acc[2][8][4] = {};

    const int KT = K>>5;
    loadA(0,0); loadB(0,0); cpcommit();
    if (KT>1){ loadA(1,32); loadB(1,32); } cpcommit();

    for (int kt=0; kt<KT; ++kt){
        cpwait1();
        __syncthreads();
        const int st = kt%3;

        #pragma unroll
        for (int ks=0; ks<2; ++ks){
            uint32_t af[2][4];
            #pragma unroll
            for (int mt=0; mt<2; ++mt){
                int r = wm*32 + mt*16 + (lane&7) + ((lane>>3)&1)*8;
                int c = ks*2 + (lane>>4);
                int csw = c ^ ((r>>1)&3);
                ldsm4(af[mt], sptr(&smA[st][(r*4+csw)*8]));
            }
            #pragma unroll
            for (int np=0; np<4; ++np){
                uint32_t bfr[4];
                int kr = ks*16 + (lane&7) + ((lane>>3)&1)*8;
                int c  = (wn*64 + np*16)/8 + (lane>>4);
                int csw = c ^ (kr&7);
                ldsm4t(bfr, sptr(&smB[st][(kr*16+csw)*8]));
                mma16816(acc[0][np*2+0], af[0], &bfr[0]);
                mma16816(acc[0][np*2+1], af[0], &bfr[2]);
                mma16816(acc[1][np*2+0], af[1], &bfr[0]);
                mma16816(acc[1][np*2+1], af[1], &bfr[2]);
            }
        }
        if (kt+2 < KT){ loadA((kt+2)%3, (kt+2)*32); loadB((kt+2)%3, (kt+2)*32); }
        cpcommit();
    }

    const int rbase = m0 + wm*32 + (lane>>2);
    const int cbase = n0 + wn*64 + (lane&3)*2;
    #pragma unroll
    for (int mt=0; mt<2; ++mt){
        #pragma unroll
        for (int nt=0; nt<8; ++nt){
            int row = rbase + mt*16;
            int col = cbase + nt*8;
            float b0 = bias[col]*bsel, b1 = bias[col+1]*bsel;
            float v0 = acc[mt][nt][0]+b0, v1 = acc[mt][nt][1]+b1;
            float v2 = acc[mt][nt][2]+b0, v3 = acc[mt][nt][3]+b1;
            if (OUTMODE==1){
                v0=fmaxf(v0,0.f); v1=fmaxf(v1,0.f); v2=fmaxf(v2,0.f); v3=fmaxf(v3,0.f);
            }
            if (OUTMODE<=1){
                bf16* C = (bf16*)Cout;
                *(bf162*)(C + (size_t)row*N + col)     = __floats2bfloat162_rn(v0,v1);
                *(bf162*)(C + (size_t)(row+8)*N + col) = __floats2bfloat162_rn(v2,v3);
            } else {
                float* C = (float*)Cout + (size_t)z*zc;
                *(float2*)(C + (size_t)row*N + col)     = make_float2(v0,v1);
                *(float2*)(C + (size_t)(row+8)*N + col) = make_float2(v2,v3);
            }
        }
    }
}

// ---------------- fused FFN gate: C = relu(A@B1+b1) * (A@B2+b2) ------------
__global__ void __launch_bounds__(256) dualgate(
    const bf16* __restrict__ A,
    const bf16* __restrict__ B1, const float* __restrict__ b1,
    const bf16* __restrict__ B2, const float* __restrict__ b2,
    bf16* __restrict__ C, int M, int N, int K)
{
    __shared__ __align__(16) bf16 smA [3][128*32];
    __shared__ __align__(16) bf16 smB1[3][32*64];
    __shared__ __align__(16) bf16 smB2[3][32*64];

    const int m0 = blockIdx.y*128, n0 = blockIdx.x*64;
    const int t = threadIdx.x;
    const int w = t>>5, lane = t&31;
    const int wm = w>>1, wn = w&1;

    auto loadA = [&](int st, int k0){
        #pragma unroll
        for (int i=0;i<2;++i){
            int idx = t + i*256;
            int r = idx>>2, c = idx&3;
            int csw = c ^ ((r>>1)&3);
            cp16(sptr(&smA[st][(r*4+csw)*8]), A + (size_t)(m0+r)*K + k0 + c*8);
        }
    };
    auto loadB = [&](int st, int k0){
        int r = t>>3, c = t&7;
        int csw = c ^ (r&7);
        cp16(sptr(&smB1[st][(r*8+csw)*8]), B1 + (size_t)(k0+r)*N + n0 + c*8);
        cp16(sptr(&smB2[st][(r*8+csw)*8]), B2 + (size_t)(k0+r)*N + n0 + c*8);
    };

    float acc1[2][4][4] = {};
    float acc2[2][4][4] = {};

    const int KT = K>>5;
    loadA(0,0); loadB(0,0); cpcommit();
    if (KT>1){ loadA(1,32); loadB(1,32); } cpcommit();

    for (int kt=0; kt<KT; ++kt){
        cpwait1();
        __syncthreads();
        const int st = kt%3;

        #pragma unroll
        for (int ks=0; ks<2; ++ks){
            uint32_t af[2][4];
            #pragma unroll
            for (int mt=0; mt<2; ++mt){
                int r = wm*32 + mt*16 + (lane&7) + ((lane>>3)&1)*8;
                int c = ks*2 + (lane>>4);
                int csw = c ^ ((r>>1)&3);
                ldsm4(af[mt], sptr(&smA[st][(r*4+csw)*8]));
            }
            #pragma unroll
            for (int np=0; np<2; ++np){
                int kr = ks*16 + (lane&7) + ((lane>>3)&1)*8;
                int c  = (wn*32 + np*16)/8 + (lane>>4);
                int csw = c ^ (kr&7);
                uint32_t f1[4], f2[4];
                ldsm4t(f1, sptr(&smB1[st][(kr*8+csw)*8]));
                ldsm4t(f2, sptr(&smB2[st][(kr*8+csw)*8]));
                mma16816(acc1[0][np*2+0], af[0], &f1[0]);
                mma16816(acc1[0][np*2+1], af[0], &f1[2]);
                mma16816(acc1[1][np*2+0], af[1], &f1[0]);
                mma16816(acc1[1][np*2+1], af[1], &f1[2]);
                mma16816(acc2[0][np*2+0], af[0], &f2[0]);
                mma16816(acc2[0][np*2+1], af[0], &f2[2]);
                mma16816(acc2[1][np*2+0], af[1], &f2[0]);
                mma16816(acc2[1][np*2+1], af[1], &f2[2]);
            }
        }
        if (kt+2 < KT){ loadA((kt+2)%3, (kt+2)*32); loadB((kt+2)%3, (kt+2)*32); }
        cpcommit();
    }

    const int rbase = m0 + wm*32 + (lane>>2);
    const int cbase = n0 + wn*32 + (lane&3)*2;
    #pragma unroll
    for (int mt=0; mt<2; ++mt){
        #pragma unroll
        for (int nt=0; nt<4; ++nt){
            int row = rbase + mt*16;
            int col = cbase + nt*8;
            float c10 = b1[col], c11 = b1[col+1];
            float c20 = b2[col], c21 = b2[col+1];
            float v0 = fmaxf(acc1[mt][nt][0]+c10, 0.f)*(acc2[mt][nt][0]+c20);
            float v1 = fmaxf(acc1[mt][nt][1]+c11, 0.f)*(acc2[mt][nt][1]+c21);
            float v2 = fmaxf(acc1[mt][nt][2]+c10, 0.f)*(acc2[mt][nt][2]+c20);
            float v3 = fmaxf(acc1[mt][nt][3]+c11, 0.f)*(acc2[mt][nt][3]+c21);
            *(bf162*)(C + (size_t)row*N + col)     = __floats2bfloat162_rn(v0,v1);
            *(bf162*)(C + (size_t)(row+8)*N + col) = __floats2bfloat162_rn(v2,v3);
        }
    }
}

// ---------------- flash attention v5: fp8 QK, bf16 PV (R12 best) ------------
#define FQ8_OFF    0
#define FK8_OFF(s) (32768 + (s)*16384)
#define FV_OFF(s)  (65536 + (s)*32768)
#define FP_OFF(s)  (131072 + (s)*16384)
#define FST_OFF    163840
#define FLASH_SMEM 165888
#define NT_        (SI_/64)
#define EXSC       0.09016844f   /* log2(e)/16 */

__global__ void __launch_bounds__(512,1) flash_bf5()
{
    extern __shared__ __align__(16) char sm[];
    const uint32_t smb = sptr(sm);
    float* es_s   = (float*)(sm + FST_OFF);
    float* rsum_s = (float*)(sm + FST_OFF + 512);
    float* psum_s = (float*)(sm + FST_OFF + 1024);

    const int t = threadIdx.x, w = t>>5, lane = t&31;
    const int h = blockIdx.y, b = blockIdx.z;
    const int m0 = blockIdx.x*128;

    auto f8off = [](int r, int c){ return (r*16 + (c ^ (r&7)))*16; };
    auto voffB = [](int r, int c){ return (r*32 + (c ^ (r&7)))*16; };
    auto pB    = [](int r, int c){ return (r*8  + (c ^ (r&7)))*16; };
    auto pE    = [](int r, int c){ return (r*8  + (c ^ (r&7)))*8;  };

    const uint8_t* q8g = g_q8 + ((size_t)h*MROWS + b*SM_ + m0)*256;
    #pragma unroll
    for (int i=0;i<4;++i){
        int idx = t + i*512;
        int r = idx>>4, c = idx&15;
        cp16(smb + FQ8_OFF + f8off(r,c), q8g + (size_t)r*256 + c*16);
    }
    auto loadK = [&](int tile, int slot){
        const uint8_t* kg = g_k8 + ((size_t)b*SI_ + tile*64)*256;
        #pragma unroll
        for (int i=0;i<2;++i){
            int idx = t + i*512;
            int r = idx>>4, c = idx&15;
            cp16(smb + FK8_OFF(slot) + f8off(r,c), kg + (size_t)r*256 + c*16);
        }
    };
    auto loadV = [&](int tile, int slot){
        const bf16* vg = g_kvb + ((size_t)b*SI_ + tile*64)*512 + 256;
        #pragma unroll
        for (int i=0;i<4;++i){
            int idx = t + i*512;
            int r = idx>>5, c = idx&31;
            cp16(smb + FV_OFF(slot) + voffB(r,c), vg + (size_t)r*512 + c*8);
        }
    };
    loadK(0,0); loadV(0,0); cpcommit();
    cpcommit();

    {
        int row = t>>2, quad = t&3;
        const bf162* q2 = (const bf162*)(g_skq + (size_t)(b*SM_ + m0 + row)*NSP + 512 + h*256 + quad*64);
        const bf162* k2 = (const bf162*)(g_skq + (size_t)(b*SM_ + m0 + row)*NSP + quad*64);
        float s = 0.f;
        #pragma unroll
        for (int j=0;j<32;++j){
            float2 qv = __bfloat1622float2(q2[j]);
            float2 kv = __bfloat1622float2(k2[j]);
            s += qv.x*kv.x + qv.y*kv.y;
        }
        s += __shfl_xor_sync(~0u, s, 1);
        s += __shfl_xor_sync(~0u, s, 2);
        if (quad==0) es_s[row] = fexp2(s*EXSC);
    }
    __syncthreads();

    const int mh = w>>2, nq = w&3;
    float o[2][8][4];
    {
        const bf16* mvb = g_skq + (size_t)(b*SM_ + m0)*NSP + 256;
        #pragma unroll
        for (int mt=0;mt<2;++mt){
            int r0 = mh*32 + mt*16 + (lane>>2);
            float e0 = es_s[r0], e1 = es_s[r0+8];
            #pragma unroll
            for (int nt=0;nt<8;++nt){
                int col = nq*64 + nt*8 + (lane&3)*2;
                float2 f0 = __bfloat1622float2(*(const bf162*)(mvb + (size_t)r0*NSP + col));
                float2 f1 = __bfloat1622float2(*(const bf162*)(mvb + (size_t)(r0+8)*NSP + col));
                o[mt][nt][0]=e0*f0.x; o[mt][nt][1]=e0*f0.y;
                o[mt][nt][2]=e1*f1.x; o[mt][nt][3]=e1*f1.y;
            }
        }
    }

    const int sw_m = w>>1, sw_n = w&1;
    float ps0 = 0.f, ps1 = 0.f;

    for (int bb=0; bb<=NT_; ++bb){
        cpwait1();
        __syncthreads();

        if (bb+1 < NT_) loadK(bb+1, (bb+1)&1);
        cpcommit();

        float sa[4][4] = {};
        if (bb < NT_){
            const uint32_t Kb = smb + FK8_OFF(bb&1);
            #pragma unroll
            for (int ks=0; ks<8; ++ks){
                uint32_t af[4];
                {
                    int r = sw_m*16 + (lane&7) + ((lane>>3)&1)*8;
                    int c = ks*2 + (lane>>4);
                    ldsm4(af, smb + FQ8_OFF + f8off(r,c));
                }
                #pragma unroll
                for (int np=0; np<2; ++np){
                    uint32_t bfr[4];
                    int r = sw_n*32 + np*16 + ((lane>>4)&1)*8 + (lane&7);
                    int c = ks*2 + ((lane>>3)&1);
                    ldsm4(bfr, Kb + f8off(r,c));
                    mma_e4m3(sa[np*2+0], af, &bfr[0]);
                    mma_e4m3(sa[np*2+1], af, &bfr[2]);
                }
            }
        }

        if (bb >= 1){
            const uint32_t Vb = smb + FV_OFF((bb-1)&1);
            const uint32_t Pb = smb + FP_OFF((bb-1)&1);
            #pragma unroll
            for (int ks=0; ks<4; ++ks){
                uint32_t af[2][4];
                #pragma unroll
                for (int mt=0;mt<2;++mt){
                    int r = mh*32 + mt*16 + (lane&7) + ((lane>>3)&1)*8;
                    int c = ks*2 + (lane>>4);
                    ldsm4(af[mt], Pb + pB(r,c));
                }
                #pragma unroll
                for (int np=0;np<4;++np){
                    uint32_t bfr[4];
                    int kr = ks*16 + (lane&7) + ((lane>>3)&1)*8;
                    int c  = (nq*64 + np*16)/8 + (lane>>4);
                    ldsm4t(bfr, Vb + voffB(kr,c));
                    mma16816(o[0][np*2+0], af[0], &bfr[0]);
                    mma16816(o[0][np*2+1], af[0], &bfr[2]);
                    mma16816(o[1][np*2+0], af[1], &bfr[0]);
                    mma16816(o[1][np*2+1], af[1], &bfr[2]);
                }
            }
        }

        if (bb < NT_){
            bf16* Pp = (bf16*)(sm + FP_OFF(bb&1));
            int r0 = sw_m*16 + (lane>>2);
            #pragma unroll
            for (int i4=0;i4<4;++i4){
                float p0 = fexp2(sa[i4][0]*EXSC);
                float p1 = fexp2(sa[i4][1]*EXSC);
                float p2 = fexp2(sa[i4][2]*EXSC);
                float p3 = fexp2(sa[i4][3]*EXSC);
                ps0 += p0 + p1;
                ps1 += p2 + p3;
                int c = sw_n*4 + i4;
                int e = (lane&3)*2;
                *(bf162*)(Pp + pE(r0,c) + e)   = __floats2bfloat162_rn(p0,p1);
                *(bf162*)(Pp + pE(r0+8,c) + e) = __floats2bfloat162_rn(p2,p3);
            }
        }

        __syncthreads();
        if (bb+1 < NT_) loadV(bb+1, (bb+1)&1);
        cpcommit();
    }

    ps0 += __shfl_xor_sync(~0u, ps0, 1);
    ps0 += __shfl_xor_sync(~0u, ps0, 2);
    ps1 += __shfl_xor_sync(~0u, ps1, 1);
    ps1 += __shfl_xor_sync(~0u, ps1, 2);
    if ((lane&3)==0){
        int r0 = sw_m*16 + (lane>>2);
        psum_s[r0*2 + sw_n]     = ps0;
        psum_s[(r0+8)*2 + sw_n] = ps1;
    }
    __syncthreads();
    if (t < 128) rsum_s[t] = es_s[t] + psum_s[t*2] + psum_s[t*2+1];
    __syncthreads();

    #pragma unroll
    for (int mt=0;mt<2;++mt){
        int r0 = mh*32 + mt*16 + (lane>>2);
        float i0 = 1.f/rsum_s[r0], i1 = 1.f/rsum_s[r0+8];
        bf16* c0 = g_ccb + ((size_t)(b*SM_ + m0 + r0)*(H_*D_)) + h*D_;
        bf16* c1 = g_ccb + ((size_t)(b*SM_ + m0 + r0 + 8)*(H_*D_)) + h*D_;
        #pragma unroll
        for (int nt=0;nt<8;++nt){
            int col = nq*64 + nt*8 + (lane&3)*2;
            *(bf162*)(c0+col) = __floats2bfloat162_rn(o[mt][nt][0]*i0, o[mt][nt][1]*i0);
            *(bf162*)(c1+col) = __floats2bfloat162_rn(o[mt][nt][2]*i1, o[mt][nt][3]*i1);
        }
    }
}

// ---------------- LayerNorm over (Y0+Y1+R) ----------------------------------
__global__ void ln3_kernel(const float* __restrict__ Y0, const float* __restrict__ Y1,
                           const float* __restrict__ R,
                           const float* __restrict__ g, const float* __restrict__ bb,
                           float* __restrict__ X, bf16* __restrict__ Xb)
{
    const int row = blockIdx.x;
    const int t = threadIdx.x;
    const size_t i = (size_t)row*D_ + t;
    const float v = Y0[i] + Y1[i] + R[i];
    __shared__ float red[8];
    __shared__ float stat;

    float s = v;
    #pragma unroll
    for (int o = 16; o; o >>= 1) s += __shfl_xor_sync(0xffffffffu, s, o);
    if ((t & 31) == 0) red[t >> 5] = s;
    __syncthreads();
    if (t == 0) {
        float tot = 0.f;
        #pragma unroll
        for (int k = 0; k < 8; ++k) tot += red[k];
        stat = tot * (1.f / D_);
    }
    __syncthreads();
    const float mean = stat;
    const float d = v - mean;

    s = d * d;
    #pragma unroll
    for (int o = 16; o; o >>= 1) s += __shfl_xor_sync(0xffffffffu, s, o);
    __syncthreads();
    if ((t & 31) == 0) red[t >> 5] = s;
    __syncthreads();
    if (t == 0) {
        float tot = 0.f;
        #pragma unroll
        for (int k = 0; k < 8; ++k) tot += red[k];
        stat = tot * (1.f / D_);
    }
    __syncthreads();
    float out = d * rsqrtf(stat + 1e-6f) * g[t] + bb[t];
    X[i] = out;
    if (Xb) Xb[i] = __float2bfloat16(out);
}

// ---------------- launch ----------------------------------------------------
extern "C" void kernel_launch(void* const* d_in, const int* in_sizes, int n_in,
                              void* d_out, int out_size)
{
    (void)in_sizes; (void)n_in; (void)out_size;
    const float* state = (const float*)d_in[0];
    const float* input = (const float*)d_in[1];
    const float* Wk    = (const float*)d_in[2];
    const float* bk    = (const float*)d_in[3];
    const float* Wv    = (const float*)d_in[4];
    const float* bv    = (const float*)d_in[5];
    const float* Wq    = (const float*)d_in[6];
    const float* bq    = (const float*)d_in[7];
    const float* Wo    = (const float*)d_in[8];
    const float* bo    = (const float*)d_in[9];
    const float* ln1g  = (const float*)d_in[10];
    const float* ln1b  = (const float*)d_in[11];
    const float* Win   = (const float*)d_in[12];
    const float* bin   = (const float*)d_in[13];
    const float* Wgnl  = (const float*)d_in[14];
    const float* bgnl  = (const float*)d_in[15];
    const float* Wgl   = (const float*)d_in[16];
    const float* bgl   = (const float*)d_in[17];
    const float* Wgo   = (const float*)d_in[18];
    const float* bgo   = (const float*)d_in[19];
    const float* ln2g  = (const float*)d_in[20];
    const float* ln2b  = (const float*)d_in[21];
    float* out = (float*)d_out;

    bf16 *ib,*sb,*Wspb,*Wob,*Winb,*Wgnlb,*Wglb,*Wgob;
    bf16 *kvb,*skq,*ccb,*xb,*hb,*gb;
    float *bsp,*yp,*x,*y2p;
    cudaGetSymbolAddress((void**)&ib,   g_ib);
    cudaGetSymbolAddress((void**)&sb,   g_sb);
    cudaGetSymbolAddress((void**)&Wspb, g_Wspb);
    cudaGetSymbolAddress((void**)&bsp,  g_bsp);
    cudaGetSymbolAddress((void**)&Wob,  g_Wob);
    cudaGetSymbolAddress((void**)&Winb, g_Winb);
    cudaGetSymbolAddress((void**)&Wgnlb,g_Wgnlb);
    cudaGetSymbolAddress((void**)&Wglb, g_Wglb);
    cudaGetSymbolAddress((void**)&Wgob, g_Wgob);
    cudaGetSymbolAddress((void**)&kvb,  g_kvb);
    cudaGetSymbolAddress((void**)&skq,  g_skq);
    cudaGetSymbolAddress((void**)&ccb,  g_ccb);
    cudaGetSymbolAddress((void**)&yp,   g_yp);
    cudaGetSymbolAddress((void**)&x,    g_x);
    cudaGetSymbolAddress((void**)&xb,   g_xb);
    cudaGetSymbolAddress((void**)&hb,   g_hb);
    cudaGetSymbolAddress((void**)&gb,   g_gb);
    cudaGetSymbolAddress((void**)&y2p,  g_y2p);

    cudaFuncSetAttribute(flash_bf5, cudaFuncAttributeMaxDynamicSharedMemorySize, FLASH_SMEM);

    dim3 blk(256);
    const long SLC = (long)MROWS*D_;
    // 0: io converts
    cvt_io<<<((IROWS+MROWS)*D_/4 + 255)/256, 256>>>(input, state);
    // 1: weight converts + packing
    cvt_w<<<(950912 + 255)/256, 256>>>(Wq, Wo, Win, Wgnl, Wgl, Wgo, Wk, Wv, bk, bv, bq);
    // 2: state merged projection [kv|q]
    gemm_bf<0><<<dim3(NSP/128, MROWS/128), blk>>>(sb, Wspb, bsp, skq, MROWS, NSP, D_, NSP, D_, 0);
    // 3: input K|V projection
    gemm_bf<0><<<dim3(4, IROWS/128), blk>>>(ib, Wspb, bsp, kvb, IROWS, 512, D_, NSP, D_, 0);
    // 4: fp8 conversion of q and k
    cvt_fp8<<<((H_*MROWS*256 + IROWS*256)/4 + 255)/256, 256>>>();
    // 5: flash attention (fp8 QK, bf16 PV)
    flash_bf5<<<dim3(SM_/128, H_, B_), 512, FLASH_SMEM>>>();
    // 6: output proj, split-K x2 (partials), then LN1 over p0+p1+state
    gemm_bf<2><<<dim3(2, MROWS/128, 2), blk>>>(ccb, Wob, bo, yp, MROWS, D_, 1024, D_, H_*D_, SLC);
    ln3_kernel<<<MROWS, D_>>>(yp, yp + SLC, state, ln1g, ln1b, x, xb);
    // FFN
    gemm_bf<1><<<dim3(FF_/128, MROWS/128), blk>>>(xb, Winb, bin, hb, MROWS, FF_, D_, FF_, D_, 0);
    dualgate<<<dim3(FF_/64, MROWS/128), blk>>>(hb, Wgnlb, bgnl, Wglb, bgl, gb, MROWS, FF_, FF_);
    // Wgo split-K x2, then LN2 over p0+p1+x
    gemm_bf<2><<<dim3(2, MROWS/128, 2), blk>>>(gb, Wgob, bgo, y2p, MROWS, D_, 512, D_, FF_, SLC);
    ln3_kernel<<<MROWS, D_>>>(y2p, y2p + SLC, x, ln2g, ln2b, out, nullptr);
}